// round 15
// baseline (speedup 1.0000x reference)
#include <cuda_runtime.h>
#include <cuda_bf16.h>
#include <cstdint>
#include <math.h>

#define BATCH   8
#define OUT_LEN 1024
#define IN_LEN  4096
#define HDIM    256
#define NROWS   (BATCH * OUT_LEN)
#define KCAT    512                 // 2*HDIM (hi|lo concatenated)

// ---------------- scratch (__device__ globals; allocation-free rule) -------
__device__ float g_rowmax[NROWS];
__device__ __align__(16) __nv_bfloat16 g_Qc  [(size_t)BATCH * OUT_LEN * KCAT];   // [b][o][hi|lo]
__device__ __align__(16) __nv_bfloat16 g_Ec  [(size_t)BATCH * IN_LEN  * KCAT];   // [b][i][hi|lo]
__device__ __align__(16) __nv_bfloat16 g_Ahi [(size_t)BATCH * OUT_LEN * IN_LEN];
__device__ __align__(16) __nv_bfloat16 g_Alo [(size_t)BATCH * OUT_LEN * IN_LEN];

// ---------------- helpers ---------------------------------------------------
__device__ __forceinline__ uint32_t smem_u32(const void* p) {
    uint32_t a;
    asm("{ .reg .u64 t; cvta.to.shared.u64 t, %1; cvt.u32.u64 %0, t; }" : "=r"(a) : "l"(p));
    return a;
}
__device__ __forceinline__ void cp16(uint32_t dst, const void* src) {
    asm volatile("cp.async.cg.shared.global [%0], [%1], 16;" :: "r"(dst), "l"(src) : "memory");
}
#define CP_COMMIT() asm volatile("cp.async.commit_group;" ::: "memory")
#define CP_WAIT1()  asm volatile("cp.async.wait_group 1;" ::: "memory")

__device__ __forceinline__ void ldmx4(uint32_t* r, uint32_t addr) {
    asm volatile("ldmatrix.sync.aligned.m8n8.x4.shared.b16 {%0,%1,%2,%3}, [%4];"
        : "=r"(r[0]), "=r"(r[1]), "=r"(r[2]), "=r"(r[3]) : "r"(addr));
}
__device__ __forceinline__ void ldmx4_t(uint32_t* r, uint32_t addr) {
    asm volatile("ldmatrix.sync.aligned.m8n8.x4.trans.shared.b16 {%0,%1,%2,%3}, [%4];"
        : "=r"(r[0]), "=r"(r[1]), "=r"(r[2]), "=r"(r[3]) : "r"(addr));
}
__device__ __forceinline__ void mma_bf16(float* c, const uint32_t* a, uint32_t b0, uint32_t b1) {
    asm volatile("mma.sync.aligned.m16n8k16.row.col.f32.bf16.bf16.f32 "
        "{%0,%1,%2,%3}, {%4,%5,%6,%7}, {%8,%9}, {%0,%1,%2,%3};"
        : "+f"(c[0]), "+f"(c[1]), "+f"(c[2]), "+f"(c[3])
        : "r"(a[0]), "r"(a[1]), "r"(a[2]), "r"(a[3]), "r"(b0), "r"(b1));
}
__device__ __forceinline__ void red_add(float* p, float v) {
    asm volatile("red.global.add.f32 [%0], %1;" :: "l"(p), "f"(v) : "memory");
}

__device__ __forceinline__ void atomicMaxFloat(float* addr, float val) {
    if (val >= 0.0f) atomicMax((int*)addr, __float_as_int(val));
    else             atomicMin((unsigned int*)addr, __float_as_uint(val));
}

// Map z-rank -> batch index so that rank 0 gets the LONGEST length.
// Deterministic tie-break by batch index. ~64 scalar ops.
__device__ __forceinline__ int batch_for_rank(const int* __restrict__ lengths, int r) {
    int L[BATCH];
#pragma unroll
    for (int j = 0; j < BATCH; j++) L[j] = lengths[j];
    int pick = 0;
#pragma unroll
    for (int j = 0; j < BATCH; j++) {
        int rank = 0;
#pragma unroll
        for (int k = 0; k < BATCH; k++)
            rank += (L[k] > L[j]) || (L[k] == L[j] && k < j);
        if (rank == r) pick = j;
    }
    return pick;
}

// ---------------------------------------------------------------------------
// Convert Q and E (fp32) to concatenated bf16 [hi(256) | lo(256)] rows.
// Also zeroes C (split-K RED target) and inits rowmax (merged init).
// ---------------------------------------------------------------------------
__global__ __launch_bounds__(256) void convert_qe_kernel(
    const float* __restrict__ Q, const float* __restrict__ E, float4* __restrict__ C4)
{
    const size_t QN4 = (size_t)BATCH * OUT_LEN * HDIM / 4;   // 524288 (= C float4 count)
    const size_t EN4 = (size_t)BATCH * IN_LEN  * HDIM / 4;   // 2097152
    size_t idx = (size_t)blockIdx.x * 256 + threadIdx.x;
    if (idx < NROWS) g_rowmax[idx] = -INFINITY;

    float4 v; __nv_bfloat16* dst; size_t e;
    if (idx < QN4) { e = idx; C4[idx] = make_float4(0.f, 0.f, 0.f, 0.f);
                     v = ((const float4*)Q)[e]; dst = g_Qc; }
    else           { e = idx - QN4; if (e >= EN4) return;
                     v = ((const float4*)E)[e]; dst = g_Ec; }
    size_t row = e >> 6;          // 64 float4 per 256-wide source row
    size_t cp  = e & 63;
    __nv_bfloat162 h01, h23, l01, l23;
    h01.x = __float2bfloat16(v.x); h01.y = __float2bfloat16(v.y);
    h23.x = __float2bfloat16(v.z); h23.y = __float2bfloat16(v.w);
    l01.x = __float2bfloat16(v.x - __bfloat162float(h01.x));
    l01.y = __float2bfloat16(v.y - __bfloat162float(h01.y));
    l23.x = __float2bfloat16(v.z - __bfloat162float(h23.x));
    l23.y = __float2bfloat16(v.w - __bfloat162float(h23.y));
    uint2 hv, lv;
    hv.x = *(uint32_t*)&h01; hv.y = *(uint32_t*)&h23;
    lv.x = *(uint32_t*)&l01; lv.y = *(uint32_t*)&l23;
    *(uint2*)(dst + row * KCAT +        cp * 4) = hv;
    *(uint2*)(dst + row * KCAT + HDIM + cp * 4) = lv;
}

// ---------------------------------------------------------------------------
// GEMM1 (HMMA): scores = Q.E^T, 3-segment split [qh,qh,ql]x[eh,el,eh].
// CTA 128x128, BK=64, NK=12, 8 warps, 3-stage cp.async, ONE sync per chunk.
// Chunk-major segment order (seg inner) for L2 reuse of hi tiles.
// Batches scheduled longest-first via z-rank remap.
// ---------------------------------------------------------------------------
#define PITCH64  144
#define G1_STAGE (128 * PITCH64)          // 18432
#define G1_SMEM  (6 * G1_STAGE)           // A[3] + B[3] = 110592
__global__ __launch_bounds__(256, 2) void score_mma_kernel(
    const int* __restrict__ lengths, float* __restrict__ attn)
{
    const int b = batch_for_rank(lengths, blockIdx.z);
    const int m0 = blockIdx.y * 128, n0 = blockIdx.x * 128;
    const int len = lengths[b];
    if (n0 >= len) return;   // fully masked: softmax writes the zeros

    extern __shared__ __align__(16) char smem[];
    const uint32_t sbase = smem_u32(smem);
    const int tid = threadIdx.x, wid = tid >> 5, lane = tid & 31;

    const char* Ag = (const char*)(g_Qc + ((size_t)b * OUT_LEN + m0) * KCAT);
    const char* Bg = (const char*)(g_Ec + ((size_t)b * IN_LEN  + n0) * KCAT);

    const int wm = (wid >> 1) * 32;      // warp m offset in tile
    const int wn = (wid & 1) * 64;       // warp n offset

    float acc[2][8][4] = {};

    // chunk-major: kc = ci*3 + seg; segments (A hi,B hi),(A hi,B lo),(A lo,B hi)
    auto issue = [&](int kc, int st) {
        int ci = kc / 3, seg = kc - ci * 3;
        uint32_t aoff = ((seg == 2) ? 512u : 0u) + ci * 128;
        uint32_t boff = ((seg == 1) ? 512u : 0u) + ci * 128;
        uint32_t a_s = sbase + st * G1_STAGE;
        uint32_t b_s = sbase + 3 * G1_STAGE + st * G1_STAGE;
#pragma unroll
        for (int r = 0; r < 4; r++) {
            int idx = tid + r * 256;
            int row = idx >> 3, c = idx & 7;
            cp16(a_s + row * PITCH64 + c * 16, Ag + (size_t)row * (KCAT * 2) + aoff + c * 16);
            cp16(b_s + row * PITCH64 + c * 16, Bg + (size_t)row * (KCAT * 2) + boff + c * 16);
        }
        CP_COMMIT();
    };

    const uint32_t a_lane_off = (wm + (lane & 15)) * PITCH64 + ((lane >> 4) & 1) * 16;
    const uint32_t b_lane_off = (wn + (lane & 7) + ((lane & 16) ? 8 : 0)) * PITCH64
                              + ((lane & 8) ? 16 : 0);

    const int NK = 12;
    issue(0, 0);
    issue(1, 1);
    int st = 0, sti = 2;
    for (int kc = 0; kc < NK; kc++) {
        CP_WAIT1();                      // group kc complete (kc+1 may be in flight)
        __syncthreads();                 // all warps finished compute(kc-1)
        if (kc + 2 < NK) issue(kc + 2, sti); else CP_COMMIT();
        uint32_t a_s = sbase + st * G1_STAGE;
        uint32_t b_s = sbase + 3 * G1_STAGE + st * G1_STAGE;
#pragma unroll
        for (int ks = 0; ks < 4; ks++) {
            uint32_t a[2][4], bf[4][4];
#pragma unroll
            for (int mt = 0; mt < 2; mt++)
                ldmx4(a[mt], a_s + a_lane_off + mt * 16 * PITCH64 + ks * 32);
#pragma unroll
            for (int np = 0; np < 4; np++)
                ldmx4(bf[np], b_s + b_lane_off + np * 16 * PITCH64 + ks * 32);
#pragma unroll
            for (int np = 0; np < 4; np++)
#pragma unroll
                for (int mt = 0; mt < 2; mt++) {
                    mma_bf16(acc[mt][2 * np],     a[mt], bf[np][0], bf[np][1]);
                    mma_bf16(acc[mt][2 * np + 1], a[mt], bf[np][2], bf[np][3]);
                }
        }
        st  = (st  == 2) ? 0 : st  + 1;
        sti = (sti == 2) ? 0 : sti + 1;
    }

    // Epilogue: mask, store raw scores, atomic rowmax.
    const int tig = lane & 3, grp = lane >> 2;
#pragma unroll
    for (int mt = 0; mt < 2; mt++) {
        int r0 = m0 + wm + mt * 16 + grp;
        int r1 = r0 + 8;
        float mx0 = -INFINITY, mx1 = -INFINITY;
        float* row0 = attn + ((size_t)b * OUT_LEN + r0) * IN_LEN;
        float* row1 = attn + ((size_t)b * OUT_LEN + r1) * IN_LEN;
#pragma unroll
        for (int nt = 0; nt < 8; nt++) {
            int col = n0 + wn + nt * 8 + 2 * tig;
            bool v0 = col < len, v1 = col + 1 < len;
            float c00 = v0 ? acc[mt][nt][0] : -INFINITY;
            float c01 = v1 ? acc[mt][nt][1] : -INFINITY;
            float c10 = v0 ? acc[mt][nt][2] : -INFINITY;
            float c11 = v1 ? acc[mt][nt][3] : -INFINITY;
            mx0 = fmaxf(mx0, fmaxf(c00, c01));
            mx1 = fmaxf(mx1, fmaxf(c10, c11));
            *(float2*)(row0 + col) = make_float2(c00, c01);
            *(float2*)(row1 + col) = make_float2(c10, c11);
        }
        mx0 = fmaxf(mx0, __shfl_xor_sync(0xffffffffu, mx0, 1));
        mx0 = fmaxf(mx0, __shfl_xor_sync(0xffffffffu, mx0, 2));
        mx1 = fmaxf(mx1, __shfl_xor_sync(0xffffffffu, mx1, 1));
        mx1 = fmaxf(mx1, __shfl_xor_sync(0xffffffffu, mx1, 2));
        if (tig == 0) {
            atomicMaxFloat(&g_rowmax[b * OUT_LEN + r0], mx0);
            atomicMaxFloat(&g_rowmax[b * OUT_LEN + r1], mx1);
        }
    }
}

// ---------------------------------------------------------------------------
// Fused softmax: normalize in place, emit bf16 hi/lo of attn (valid cols only).
// Rows scheduled longest-batch-first (same remap as the GEMMs).
// bf16 zero tail extends to 64-element chunk boundary (GEMM2 BK=64).
// ---------------------------------------------------------------------------
__global__ __launch_bounds__(256) void softmax_kernel(
    const int* __restrict__ lengths, float* __restrict__ attn)
{
    __shared__ float buf[IN_LEN];
    __shared__ float red[8];
    int b   = batch_for_rank(lengths, blockIdx.x >> 10);
    int row = b * OUT_LEN + (blockIdx.x & (OUT_LEN - 1));
    int len = lengths[b];
    int nv4 = (len + 3) >> 2;              // float4s with any valid element
    int np4 = ((len + 63) >> 6) << 4;      // float4s covering ceil(len/64)*64
    size_t rowoff = (size_t)row * IN_LEN;
    float* s = attn + rowoff;
    float m = g_rowmax[row];

    float sum = 0.0f;
    for (int i = threadIdx.x; i < nv4; i += 256) {
        float4 v = ((const float4*)s)[i];
        float e0 = __expf(v.x - m), e1 = __expf(v.y - m);
        float e2 = __expf(v.z - m), e3 = __expf(v.w - m);
        ((float4*)buf)[i] = make_float4(e0, e1, e2, e3);
        sum += e0 + e1 + e2 + e3;
    }
#pragma unroll
    for (int off = 16; off > 0; off >>= 1)
        sum += __shfl_xor_sync(0xffffffffu, sum, off);
    if ((threadIdx.x & 31) == 0) red[threadIdx.x >> 5] = sum;
    __syncthreads();
    float tot = 0.0f;
#pragma unroll
    for (int i = 0; i < 8; i++) tot += red[i];
    float inv = 1.0f / tot;

    __nv_bfloat162* ah = (__nv_bfloat162*)(g_Ahi + rowoff);
    __nv_bfloat162* al = (__nv_bfloat162*)(g_Alo + rowoff);
    for (int i = threadIdx.x; i < nv4; i += 256) {
        float4 v = ((const float4*)buf)[i];
        v.x *= inv; v.y *= inv; v.z *= inv; v.w *= inv;
        ((float4*)s)[i] = v;
        __nv_bfloat162 h01, h23, l01, l23;
        h01.x = __float2bfloat16(v.x); h01.y = __float2bfloat16(v.y);
        h23.x = __float2bfloat16(v.z); h23.y = __float2bfloat16(v.w);
        l01.x = __float2bfloat16(v.x - __bfloat162float(h01.x));
        l01.y = __float2bfloat16(v.y - __bfloat162float(h01.y));
        l23.x = __float2bfloat16(v.z - __bfloat162float(h23.x));
        l23.y = __float2bfloat16(v.w - __bfloat162float(h23.y));
        ah[i * 2] = h01; ah[i * 2 + 1] = h23;
        al[i * 2] = l01; al[i * 2 + 1] = l23;
    }
    // masked tail: fp32 zeros (required output), bf16 zeros to chunk boundary
    for (int i = nv4 + threadIdx.x; i < IN_LEN / 4; i += 256) {
        ((float4*)s)[i] = make_float4(0.f, 0.f, 0.f, 0.f);
        if (i < np4) {
            __nv_bfloat162 z; z.x = __float2bfloat16(0.f); z.y = z.x;
            ah[i * 2] = z; ah[i * 2 + 1] = z;
            al[i * 2] = z; al[i * 2 + 1] = z;
        }
    }
}

// ---------------------------------------------------------------------------
// GEMM2 (HMMA): context = attn.E, 3-segment split, split-K=4.
// CTA 128x128 (n over HDIM), warp 32x64, BK=64, 3-stage cp.async, one sync.
// Chunk-major segment order (seg inner) for L2 reuse of hi tiles.
// B fragments straight from K-major Ec via ldmatrix.trans.
// All splits RED-accumulate into zero-initialized C.
// Batches scheduled longest-first via z-rank remap.
// ---------------------------------------------------------------------------
#define BPITCH    272
#define G2_ASTAGE (128 * PITCH64)        // 18432
#define G2_BSTAGE (64 * BPITCH)          // 17408
#define G2_SMEM   (3 * G2_ASTAGE + 3 * G2_BSTAGE)   // 107520
__global__ __launch_bounds__(256, 2) void ctx_mma_kernel(
    const int* __restrict__ lengths, float* __restrict__ C)
{
    extern __shared__ __align__(16) char smem[];
    const uint32_t sbase = smem_u32(smem);
    const int tid = threadIdx.x, wid = tid >> 5, lane = tid & 31;
    const int b = batch_for_rank(lengths, blockIdx.z >> 2);
    const int kz = blockIdx.z & 3;
    const int m0 = blockIdx.y * 128, n0 = blockIdx.x * 128;
    const int len = lengths[b];
    const int nc = (len + 63) >> 6;          // valid 64-element K chunks
    const int quarter = (nc + 3) >> 2;
    const int lo = kz * quarter;
    const int hi = (nc < lo + quarter) ? nc : (lo + quarter);
    const int cnt = (hi > lo) ? (hi - lo) : 0;
    const int NK = 3 * cnt;
    if (NK == 0) return;                     // nothing to add (C pre-zeroed)

    const char* Ahi = (const char*)(g_Ahi + ((size_t)b * OUT_LEN + m0) * IN_LEN);
    const char* Alo = (const char*)(g_Alo + ((size_t)b * OUT_LEN + m0) * IN_LEN);
    const char* Eg  = (const char*)(g_Ec  + (size_t)b * IN_LEN * KCAT);

    const int wm = (wid >> 1) * 32;
    const int wn = (wid & 1) * 64;

    float acc[2][8][4] = {};

    // chunk-major: kc = ci*3 + seg; segments (Ahi,Ehi),(Ahi,Elo),(Alo,Ehi)
    auto issue = [&](int kc, int st) {
        int ci  = kc / 3, seg = kc - ci * 3;
        int gci = lo + ci;                   // global 64-elem chunk index
        const char* Ab = (seg == 2) ? Alo : Ahi;
        uint32_t bcol = (uint32_t)(n0 + ((seg == 1) ? HDIM : 0)) * 2;
        uint32_t a_s = sbase + st * G2_ASTAGE;
        uint32_t b_s = sbase + 3 * G2_ASTAGE + st * G2_BSTAGE;
#pragma unroll
        for (int r = 0; r < 4; r++) {
            int idx = tid + r * 256;
            {   // A: 128 rows x 128B
                int row = idx >> 3, c = idx & 7;
                cp16(a_s + row * PITCH64 + c * 16,
                     Ab + (size_t)row * (IN_LEN * 2) + (size_t)gci * 128 + c * 16);
            }
            {   // B: 64 k-rows x 256B from Ec rows i = gci*64 + row
                int row = idx >> 4, c = idx & 15;
                cp16(b_s + row * BPITCH + c * 16,
                     Eg + ((size_t)gci * 64 + row) * (KCAT * 2) + bcol + c * 16);
            }
        }
        CP_COMMIT();
    };

    const uint32_t a_lane_off = (wm + (lane & 15)) * PITCH64 + ((lane >> 4) & 1) * 16;
    // trans-B: lane groups address k-rows of [k][n] tiles
    const uint32_t b_lane_off = ((lane & 7) + ((lane & 8) ? 8 : 0)) * BPITCH
                              + (wn + ((lane & 16) ? 8 : 0)) * 2;

    issue(0, 0);
    if (NK > 1) issue(1, 1); else CP_COMMIT();
    int st = 0, sti = 2;
    for (int kc = 0; kc < NK; kc++) {
        CP_WAIT1();
        __syncthreads();
        if (kc + 2 < NK) issue(kc + 2, sti); else CP_COMMIT();
        uint32_t a_s = sbase + st * G2_ASTAGE;
        uint32_t b_s = sbase + 3 * G2_ASTAGE + st * G2_BSTAGE;
#pragma unroll
        for (int ks = 0; ks < 4; ks++) {
            uint32_t a[2][4], bf[4][4];
#pragma unroll
            for (int mt = 0; mt < 2; mt++)
                ldmx4(a[mt], a_s + a_lane_off + mt * 16 * PITCH64 + ks * 32);
#pragma unroll
            for (int np = 0; np < 4; np++)
                ldmx4_t(bf[np], b_s + b_lane_off + ks * 16 * BPITCH + np * 32);
#pragma unroll
            for (int np = 0; np < 4; np++)
#pragma unroll
                for (int mt = 0; mt < 2; mt++) {
                    mma_bf16(acc[mt][2 * np],     a[mt], bf[np][0], bf[np][1]);
                    mma_bf16(acc[mt][2 * np + 1], a[mt], bf[np][2], bf[np][3]);
                }
        }
        st  = (st  == 2) ? 0 : st  + 1;
        sti = (sti == 2) ? 0 : sti + 1;
    }

    const int tig = lane & 3, grp = lane >> 2;
#pragma unroll
    for (int mt = 0; mt < 2; mt++) {
        int r0 = m0 + wm + mt * 16 + grp;
        int r1 = r0 + 8;
        float* row0 = C + ((size_t)b * OUT_LEN + r0) * HDIM;
        float* row1 = C + ((size_t)b * OUT_LEN + r1) * HDIM;
#pragma unroll
        for (int nt = 0; nt < 8; nt++) {
            int col = n0 + wn + nt * 8 + 2 * tig;
            red_add(row0 + col,     acc[mt][nt][0]);
            red_add(row0 + col + 1, acc[mt][nt][1]);
            red_add(row1 + col,     acc[mt][nt][2]);
            red_add(row1 + col + 1, acc[mt][nt][3]);
        }
    }
}

// ---------------------------------------------------------------------------
extern "C" void kernel_launch(void* const* d_in, const int* in_sizes, int n_in,
                              void* d_out, int out_size)
{
    const float* Q       = (const float*)d_in[0];   // output  [B, OUT_LEN, H]
    const float* E       = (const float*)d_in[1];   // encoder [B, IN_LEN, H]
    const int*   lengths = (const int*)  d_in[2];   // [B]

    float* ctx  = (float*)d_out;
    float* attn = ctx + (size_t)BATCH * OUT_LEN * HDIM;

    cudaFuncSetAttribute(score_mma_kernel, cudaFuncAttributeMaxDynamicSharedMemorySize, G1_SMEM);
    cudaFuncSetAttribute(ctx_mma_kernel,   cudaFuncAttributeMaxDynamicSharedMemorySize, G2_SMEM);

    size_t totf4 = ((size_t)BATCH * OUT_LEN * HDIM + (size_t)BATCH * IN_LEN * HDIM) / 4;
    convert_qe_kernel<<<(unsigned)((totf4 + 255) / 256), 256>>>(Q, E, (float4*)ctx);

    dim3 g1(IN_LEN / 128, OUT_LEN / 128, BATCH);   // (32, 8, 8)
    score_mma_kernel<<<g1, 256, G1_SMEM>>>(lengths, attn);

    softmax_kernel<<<NROWS, 256>>>(lengths, attn);

    dim3 g2(HDIM / 128, OUT_LEN / 128, BATCH * 4); // (2, 8, 32) split-K=4
    ctx_mma_kernel<<<g2, 256, G2_SMEM>>>(lengths, ctx);
}

// round 16
// speedup vs baseline: 1.0122x; 1.0122x over previous
#include <cuda_runtime.h>
#include <cuda_bf16.h>
#include <cstdint>
#include <math.h>

#define BATCH   8
#define OUT_LEN 1024
#define IN_LEN  4096
#define HDIM    256
#define NROWS   (BATCH * OUT_LEN)
#define KCAT    512                 // 2*HDIM (hi|lo concatenated)

// ---------------- scratch (__device__ globals; allocation-free rule) -------
__device__ float g_rowmax[NROWS];
__device__ __align__(16) __nv_bfloat16 g_Qc  [(size_t)BATCH * OUT_LEN * KCAT];   // [b][o][hi|lo]
__device__ __align__(16) __nv_bfloat16 g_Ec  [(size_t)BATCH * IN_LEN  * KCAT];   // [b][i][hi|lo]
__device__ __align__(16) __nv_bfloat16 g_Ahi [(size_t)BATCH * OUT_LEN * IN_LEN];
__device__ __align__(16) __nv_bfloat16 g_Alo [(size_t)BATCH * OUT_LEN * IN_LEN];

// ---------------- helpers ---------------------------------------------------
__device__ __forceinline__ uint32_t smem_u32(const void* p) {
    uint32_t a;
    asm("{ .reg .u64 t; cvta.to.shared.u64 t, %1; cvt.u32.u64 %0, t; }" : "=r"(a) : "l"(p));
    return a;
}
__device__ __forceinline__ void cp16(uint32_t dst, const void* src) {
    asm volatile("cp.async.cg.shared.global [%0], [%1], 16;" :: "r"(dst), "l"(src) : "memory");
}
#define CP_COMMIT() asm volatile("cp.async.commit_group;" ::: "memory")
#define CP_WAIT1()  asm volatile("cp.async.wait_group 1;" ::: "memory")

__device__ __forceinline__ void ldmx4(uint32_t* r, uint32_t addr) {
    asm volatile("ldmatrix.sync.aligned.m8n8.x4.shared.b16 {%0,%1,%2,%3}, [%4];"
        : "=r"(r[0]), "=r"(r[1]), "=r"(r[2]), "=r"(r[3]) : "r"(addr));
}
__device__ __forceinline__ void ldmx4_t(uint32_t* r, uint32_t addr) {
    asm volatile("ldmatrix.sync.aligned.m8n8.x4.trans.shared.b16 {%0,%1,%2,%3}, [%4];"
        : "=r"(r[0]), "=r"(r[1]), "=r"(r[2]), "=r"(r[3]) : "r"(addr));
}
__device__ __forceinline__ void mma_bf16(float* c, const uint32_t* a, uint32_t b0, uint32_t b1) {
    asm volatile("mma.sync.aligned.m16n8k16.row.col.f32.bf16.bf16.f32 "
        "{%0,%1,%2,%3}, {%4,%5,%6,%7}, {%8,%9}, {%0,%1,%2,%3};"
        : "+f"(c[0]), "+f"(c[1]), "+f"(c[2]), "+f"(c[3])
        : "r"(a[0]), "r"(a[1]), "r"(a[2]), "r"(a[3]), "r"(b0), "r"(b1));
}
__device__ __forceinline__ void red_add(float* p, float v) {
    asm volatile("red.global.add.f32 [%0], %1;" :: "l"(p), "f"(v) : "memory");
}

__device__ __forceinline__ void atomicMaxFloat(float* addr, float val) {
    if (val >= 0.0f) atomicMax((int*)addr, __float_as_int(val));
    else             atomicMin((unsigned int*)addr, __float_as_uint(val));
}

// Map z-rank -> batch index so that rank 0 gets the LONGEST length.
__device__ __forceinline__ int batch_for_rank(const int* __restrict__ lengths, int r) {
    int L[BATCH];
#pragma unroll
    for (int j = 0; j < BATCH; j++) L[j] = lengths[j];
    int pick = 0;
#pragma unroll
    for (int j = 0; j < BATCH; j++) {
        int rank = 0;
#pragma unroll
        for (int k = 0; k < BATCH; k++)
            rank += (L[k] > L[j]) || (L[k] == L[j] && k < j);
        if (rank == r) pick = j;
    }
    return pick;
}

// ---------------------------------------------------------------------------
// Convert Q and E (fp32) to concatenated bf16 [hi(256) | lo(256)] rows.
// Also zeroes C (split-K RED target) and inits rowmax (merged init).
// ---------------------------------------------------------------------------
__global__ __launch_bounds__(256) void convert_qe_kernel(
    const float* __restrict__ Q, const float* __restrict__ E, float4* __restrict__ C4)
{
    const size_t QN4 = (size_t)BATCH * OUT_LEN * HDIM / 4;   // 524288 (= C float4 count)
    const size_t EN4 = (size_t)BATCH * IN_LEN  * HDIM / 4;   // 2097152
    size_t idx = (size_t)blockIdx.x * 256 + threadIdx.x;
    if (idx < NROWS) g_rowmax[idx] = -INFINITY;

    float4 v; __nv_bfloat16* dst; size_t e;
    if (idx < QN4) { e = idx; C4[idx] = make_float4(0.f, 0.f, 0.f, 0.f);
                     v = ((const float4*)Q)[e]; dst = g_Qc; }
    else           { e = idx - QN4; if (e >= EN4) return;
                     v = ((const float4*)E)[e]; dst = g_Ec; }
    size_t row = e >> 6;          // 64 float4 per 256-wide source row
    size_t cp  = e & 63;
    __nv_bfloat162 h01, h23, l01, l23;
    h01.x = __float2bfloat16(v.x); h01.y = __float2bfloat16(v.y);
    h23.x = __float2bfloat16(v.z); h23.y = __float2bfloat16(v.w);
    l01.x = __float2bfloat16(v.x - __bfloat162float(h01.x));
    l01.y = __float2bfloat16(v.y - __bfloat162float(h01.y));
    l23.x = __float2bfloat16(v.z - __bfloat162float(h23.x));
    l23.y = __float2bfloat16(v.w - __bfloat162float(h23.y));
    uint2 hv, lv;
    hv.x = *(uint32_t*)&h01; hv.y = *(uint32_t*)&h23;
    lv.x = *(uint32_t*)&l01; lv.y = *(uint32_t*)&l23;
    *(uint2*)(dst + row * KCAT +        cp * 4) = hv;
    *(uint2*)(dst + row * KCAT + HDIM + cp * 4) = lv;
}

// ---------------------------------------------------------------------------
// GEMM1 (HMMA): scores = Q.E^T, 3-segment split [qh,qh,ql]x[eh,el,eh].
// CTA 128x128, BK=64, NK=12, 8 warps, 3-stage cp.async, ONE sync per chunk.
// Chunk-major segment order. Batches longest-first.
// Fully-masked tiles zero-fill attn (softmax no longer writes fp32 tails).
// Partially-masked columns store 0.0f (masked -inf used only for rowmax).
// ---------------------------------------------------------------------------
#define PITCH64  144
#define G1_STAGE (128 * PITCH64)          // 18432
#define G1_SMEM  (6 * G1_STAGE)           // A[3] + B[3] = 110592
__global__ __launch_bounds__(256, 2) void score_mma_kernel(
    const int* __restrict__ lengths, float* __restrict__ attn)
{
    const int b = batch_for_rank(lengths, blockIdx.z);
    const int m0 = blockIdx.y * 128, n0 = blockIdx.x * 128;
    const int len = lengths[b];
    const int tid = threadIdx.x;

    if (n0 >= len) {
        // fully masked: write the zeros here (score has DRAM headroom)
        float* base = attn + ((size_t)b * OUT_LEN + m0) * IN_LEN + n0;
        float4 z = make_float4(0.f, 0.f, 0.f, 0.f);
        for (int f = tid; f < 128 * 32; f += 256) {
            int row = f >> 5, c = f & 31;
            *reinterpret_cast<float4*>(base + (size_t)row * IN_LEN + c * 4) = z;
        }
        return;
    }

    extern __shared__ __align__(16) char smem[];
    const uint32_t sbase = smem_u32(smem);
    const int wid = tid >> 5, lane = tid & 31;

    const char* Ag = (const char*)(g_Qc + ((size_t)b * OUT_LEN + m0) * KCAT);
    const char* Bg = (const char*)(g_Ec + ((size_t)b * IN_LEN  + n0) * KCAT);

    const int wm = (wid >> 1) * 32;      // warp m offset in tile
    const int wn = (wid & 1) * 64;       // warp n offset

    float acc[2][8][4] = {};

    // chunk-major: kc = ci*3 + seg; segments (A hi,B hi),(A hi,B lo),(A lo,B hi)
    auto issue = [&](int kc, int st) {
        int ci = kc / 3, seg = kc - ci * 3;
        uint32_t aoff = ((seg == 2) ? 512u : 0u) + ci * 128;
        uint32_t boff = ((seg == 1) ? 512u : 0u) + ci * 128;
        uint32_t a_s = sbase + st * G1_STAGE;
        uint32_t b_s = sbase + 3 * G1_STAGE + st * G1_STAGE;
#pragma unroll
        for (int r = 0; r < 4; r++) {
            int idx = tid + r * 256;
            int row = idx >> 3, c = idx & 7;
            cp16(a_s + row * PITCH64 + c * 16, Ag + (size_t)row * (KCAT * 2) + aoff + c * 16);
            cp16(b_s + row * PITCH64 + c * 16, Bg + (size_t)row * (KCAT * 2) + boff + c * 16);
        }
        CP_COMMIT();
    };

    const uint32_t a_lane_off = (wm + (lane & 15)) * PITCH64 + ((lane >> 4) & 1) * 16;
    const uint32_t b_lane_off = (wn + (lane & 7) + ((lane & 16) ? 8 : 0)) * PITCH64
                              + ((lane & 8) ? 16 : 0);

    const int NK = 12;
    issue(0, 0);
    issue(1, 1);
    int st = 0, sti = 2;
    for (int kc = 0; kc < NK; kc++) {
        CP_WAIT1();
        __syncthreads();
        if (kc + 2 < NK) issue(kc + 2, sti); else CP_COMMIT();
        uint32_t a_s = sbase + st * G1_STAGE;
        uint32_t b_s = sbase + 3 * G1_STAGE + st * G1_STAGE;
#pragma unroll
        for (int ks = 0; ks < 4; ks++) {
            uint32_t a[2][4], bf[4][4];
#pragma unroll
            for (int mt = 0; mt < 2; mt++)
                ldmx4(a[mt], a_s + a_lane_off + mt * 16 * PITCH64 + ks * 32);
#pragma unroll
            for (int np = 0; np < 4; np++)
                ldmx4(bf[np], b_s + b_lane_off + np * 16 * PITCH64 + ks * 32);
#pragma unroll
            for (int np = 0; np < 4; np++)
#pragma unroll
                for (int mt = 0; mt < 2; mt++) {
                    mma_bf16(acc[mt][2 * np],     a[mt], bf[np][0], bf[np][1]);
                    mma_bf16(acc[mt][2 * np + 1], a[mt], bf[np][2], bf[np][3]);
                }
        }
        st  = (st  == 2) ? 0 : st  + 1;
        sti = (sti == 2) ? 0 : sti + 1;
    }

    // Epilogue: store masked cols as 0.0f; rowmax over valid cols only.
    const int tig = lane & 3, grp = lane >> 2;
#pragma unroll
    for (int mt = 0; mt < 2; mt++) {
        int r0 = m0 + wm + mt * 16 + grp;
        int r1 = r0 + 8;
        float mx0 = -INFINITY, mx1 = -INFINITY;
        float* row0 = attn + ((size_t)b * OUT_LEN + r0) * IN_LEN;
        float* row1 = attn + ((size_t)b * OUT_LEN + r1) * IN_LEN;
#pragma unroll
        for (int nt = 0; nt < 8; nt++) {
            int col = n0 + wn + nt * 8 + 2 * tig;
            bool v0 = col < len, v1 = col + 1 < len;
            float c00 = acc[mt][nt][0], c01 = acc[mt][nt][1];
            float c10 = acc[mt][nt][2], c11 = acc[mt][nt][3];
            mx0 = fmaxf(mx0, fmaxf(v0 ? c00 : -INFINITY, v1 ? c01 : -INFINITY));
            mx1 = fmaxf(mx1, fmaxf(v0 ? c10 : -INFINITY, v1 ? c11 : -INFINITY));
            *(float2*)(row0 + col) = make_float2(v0 ? c00 : 0.f, v1 ? c01 : 0.f);
            *(float2*)(row1 + col) = make_float2(v0 ? c10 : 0.f, v1 ? c11 : 0.f);
        }
        mx0 = fmaxf(mx0, __shfl_xor_sync(0xffffffffu, mx0, 1));
        mx0 = fmaxf(mx0, __shfl_xor_sync(0xffffffffu, mx0, 2));
        mx1 = fmaxf(mx1, __shfl_xor_sync(0xffffffffu, mx1, 1));
        mx1 = fmaxf(mx1, __shfl_xor_sync(0xffffffffu, mx1, 2));
        if (tig == 0) {
            atomicMaxFloat(&g_rowmax[b * OUT_LEN + r0], mx0);
            atomicMaxFloat(&g_rowmax[b * OUT_LEN + r1], mx1);
        }
    }
}

// ---------------------------------------------------------------------------
// Fused softmax: normalize valid region in place (masked elements inside the
// boundary float4 handled per-element), emit bf16 hi/lo. NO fp32 tail writes
// (score already zeroed everything beyond len). bf16 zeros to 64-boundary.
// ---------------------------------------------------------------------------
__global__ __launch_bounds__(256) void softmax_kernel(
    const int* __restrict__ lengths, float* __restrict__ attn)
{
    __shared__ float buf[IN_LEN];
    __shared__ float red[8];
    int row = blockIdx.x;
    int len = lengths[row >> 10];          // OUT_LEN = 1024 rows per batch
    int nv4 = (len + 3) >> 2;              // float4s containing any valid element
    int np4 = ((len + 63) >> 6) << 4;      // float4s covering ceil(len/64)*64
    size_t rowoff = (size_t)row * IN_LEN;
    float* s = attn + rowoff;
    float m = g_rowmax[row];

    float sum = 0.0f;
    for (int i = threadIdx.x; i < nv4; i += 256) {
        float4 v = ((const float4*)s)[i];
        int base = i * 4;
        float e0 = (base     < len) ? __expf(v.x - m) : 0.f;
        float e1 = (base + 1 < len) ? __expf(v.y - m) : 0.f;
        float e2 = (base + 2 < len) ? __expf(v.z - m) : 0.f;
        float e3 = (base + 3 < len) ? __expf(v.w - m) : 0.f;
        ((float4*)buf)[i] = make_float4(e0, e1, e2, e3);
        sum += e0 + e1 + e2 + e3;
    }
#pragma unroll
    for (int off = 16; off > 0; off >>= 1)
        sum += __shfl_xor_sync(0xffffffffu, sum, off);
    if ((threadIdx.x & 31) == 0) red[threadIdx.x >> 5] = sum;
    __syncthreads();
    float tot = 0.0f;
#pragma unroll
    for (int i = 0; i < 8; i++) tot += red[i];
    float inv = 1.0f / tot;

    __nv_bfloat162* ah = (__nv_bfloat162*)(g_Ahi + rowoff);
    __nv_bfloat162* al = (__nv_bfloat162*)(g_Alo + rowoff);
    for (int i = threadIdx.x; i < nv4; i += 256) {
        float4 v = ((const float4*)buf)[i];
        v.x *= inv; v.y *= inv; v.z *= inv; v.w *= inv;
        ((float4*)s)[i] = v;
        __nv_bfloat162 h01, h23, l01, l23;
        h01.x = __float2bfloat16(v.x); h01.y = __float2bfloat16(v.y);
        h23.x = __float2bfloat16(v.z); h23.y = __float2bfloat16(v.w);
        l01.x = __float2bfloat16(v.x - __bfloat162float(h01.x));
        l01.y = __float2bfloat16(v.y - __bfloat162float(h01.y));
        l23.x = __float2bfloat16(v.z - __bfloat162float(h23.x));
        l23.y = __float2bfloat16(v.w - __bfloat162float(h23.y));
        ah[i * 2] = h01; ah[i * 2 + 1] = h23;
        al[i * 2] = l01; al[i * 2 + 1] = l23;
    }
    // bf16 zero tail only (fp32 tail already zeroed by score)
    for (int i = nv4 + threadIdx.x; i < np4; i += 256) {
        __nv_bfloat162 z; z.x = __float2bfloat16(0.f); z.y = z.x;
        ah[i * 2] = z; ah[i * 2 + 1] = z;
        al[i * 2] = z; al[i * 2 + 1] = z;
    }
}

// ---------------------------------------------------------------------------
// GEMM2 (HMMA): context = attn.E, 3-segment split, split-K=4.
// CTA 128x128, warp 32x64, BK=64, 3-stage cp.async, one sync, chunk-major.
// B fragments straight from K-major Ec via ldmatrix.trans.
// All splits RED-accumulate into zero-initialized C. Batches longest-first.
// ---------------------------------------------------------------------------
#define BPITCH    272
#define G2_ASTAGE (128 * PITCH64)        // 18432
#define G2_BSTAGE (64 * BPITCH)          // 17408
#define G2_SMEM   (3 * G2_ASTAGE + 3 * G2_BSTAGE)   // 107520
__global__ __launch_bounds__(256, 2) void ctx_mma_kernel(
    const int* __restrict__ lengths, float* __restrict__ C)
{
    extern __shared__ __align__(16) char smem[];
    const uint32_t sbase = smem_u32(smem);
    const int tid = threadIdx.x, wid = tid >> 5, lane = tid & 31;
    const int b = batch_for_rank(lengths, blockIdx.z >> 2);
    const int kz = blockIdx.z & 3;
    const int m0 = blockIdx.y * 128, n0 = blockIdx.x * 128;
    const int len = lengths[b];
    const int nc = (len + 63) >> 6;          // valid 64-element K chunks
    const int quarter = (nc + 3) >> 2;
    const int lo = kz * quarter;
    const int hi = (nc < lo + quarter) ? nc : (lo + quarter);
    const int cnt = (hi > lo) ? (hi - lo) : 0;
    const int NK = 3 * cnt;
    if (NK == 0) return;                     // nothing to add (C pre-zeroed)

    const char* Ahi = (const char*)(g_Ahi + ((size_t)b * OUT_LEN + m0) * IN_LEN);
    const char* Alo = (const char*)(g_Alo + ((size_t)b * OUT_LEN + m0) * IN_LEN);
    const char* Eg  = (const char*)(g_Ec  + (size_t)b * IN_LEN * KCAT);

    const int wm = (wid >> 1) * 32;
    const int wn = (wid & 1) * 64;

    float acc[2][8][4] = {};

    // chunk-major: kc = ci*3 + seg; segments (Ahi,Ehi),(Ahi,Elo),(Alo,Ehi)
    auto issue = [&](int kc, int st) {
        int ci  = kc / 3, seg = kc - ci * 3;
        int gci = lo + ci;                   // global 64-elem chunk index
        const char* Ab = (seg == 2) ? Alo : Ahi;
        uint32_t bcol = (uint32_t)(n0 + ((seg == 1) ? HDIM : 0)) * 2;
        uint32_t a_s = sbase + st * G2_ASTAGE;
        uint32_t b_s = sbase + 3 * G2_ASTAGE + st * G2_BSTAGE;
#pragma unroll
        for (int r = 0; r < 4; r++) {
            int idx = tid + r * 256;
            {   // A: 128 rows x 128B
                int row = idx >> 3, c = idx & 7;
                cp16(a_s + row * PITCH64 + c * 16,
                     Ab + (size_t)row * (IN_LEN * 2) + (size_t)gci * 128 + c * 16);
            }
            {   // B: 64 k-rows x 256B from Ec rows i = gci*64 + row
                int row = idx >> 4, c = idx & 15;
                cp16(b_s + row * BPITCH + c * 16,
                     Eg + ((size_t)gci * 64 + row) * (KCAT * 2) + bcol + c * 16);
            }
        }
        CP_COMMIT();
    };

    const uint32_t a_lane_off = (wm + (lane & 15)) * PITCH64 + ((lane >> 4) & 1) * 16;
    const uint32_t b_lane_off = ((lane & 7) + ((lane & 8) ? 8 : 0)) * BPITCH
                              + (wn + ((lane & 16) ? 8 : 0)) * 2;

    issue(0, 0);
    if (NK > 1) issue(1, 1); else CP_COMMIT();
    int st = 0, sti = 2;
    for (int kc = 0; kc < NK; kc++) {
        CP_WAIT1();
        __syncthreads();
        if (kc + 2 < NK) issue(kc + 2, sti); else CP_COMMIT();
        uint32_t a_s = sbase + st * G2_ASTAGE;
        uint32_t b_s = sbase + 3 * G2_ASTAGE + st * G2_BSTAGE;
#pragma unroll
        for (int ks = 0; ks < 4; ks++) {
            uint32_t a[2][4], bf[4][4];
#pragma unroll
            for (int mt = 0; mt < 2; mt++)
                ldmx4(a[mt], a_s + a_lane_off + mt * 16 * PITCH64 + ks * 32);
#pragma unroll
            for (int np = 0; np < 4; np++)
                ldmx4_t(bf[np], b_s + b_lane_off + ks * 16 * BPITCH + np * 32);
#pragma unroll
            for (int np = 0; np < 4; np++)
#pragma unroll
                for (int mt = 0; mt < 2; mt++) {
                    mma_bf16(acc[mt][2 * np],     a[mt], bf[np][0], bf[np][1]);
                    mma_bf16(acc[mt][2 * np + 1], a[mt], bf[np][2], bf[np][3]);
                }
        }
        st  = (st  == 2) ? 0 : st  + 1;
        sti = (sti == 2) ? 0 : sti + 1;
    }

    const int tig = lane & 3, grp = lane >> 2;
#pragma unroll
    for (int mt = 0; mt < 2; mt++) {
        int r0 = m0 + wm + mt * 16 + grp;
        int r1 = r0 + 8;
        float* row0 = C + ((size_t)b * OUT_LEN + r0) * HDIM;
        float* row1 = C + ((size_t)b * OUT_LEN + r1) * HDIM;
#pragma unroll
        for (int nt = 0; nt < 8; nt++) {
            int col = n0 + wn + nt * 8 + 2 * tig;
            red_add(row0 + col,     acc[mt][nt][0]);
            red_add(row0 + col + 1, acc[mt][nt][1]);
            red_add(row1 + col,     acc[mt][nt][2]);
            red_add(row1 + col + 1, acc[mt][nt][3]);
        }
    }
}

// ---------------------------------------------------------------------------
extern "C" void kernel_launch(void* const* d_in, const int* in_sizes, int n_in,
                              void* d_out, int out_size)
{
    const float* Q       = (const float*)d_in[0];   // output  [B, OUT_LEN, H]
    const float* E       = (const float*)d_in[1];   // encoder [B, IN_LEN, H]
    const int*   lengths = (const int*)  d_in[2];   // [B]

    float* ctx  = (float*)d_out;
    float* attn = ctx + (size_t)BATCH * OUT_LEN * HDIM;

    cudaFuncSetAttribute(score_mma_kernel, cudaFuncAttributeMaxDynamicSharedMemorySize, G1_SMEM);
    cudaFuncSetAttribute(ctx_mma_kernel,   cudaFuncAttributeMaxDynamicSharedMemorySize, G2_SMEM);

    size_t totf4 = ((size_t)BATCH * OUT_LEN * HDIM + (size_t)BATCH * IN_LEN * HDIM) / 4;
    convert_qe_kernel<<<(unsigned)((totf4 + 255) / 256), 256>>>(Q, E, (float4*)ctx);

    dim3 g1(IN_LEN / 128, OUT_LEN / 128, BATCH);   // (32, 8, 8)
    score_mma_kernel<<<g1, 256, G1_SMEM>>>(lengths, attn);

    softmax_kernel<<<NROWS, 256>>>(lengths, attn);

    dim3 g2(HDIM / 128, OUT_LEN / 128, BATCH * 4); // (2, 8, 32) split-K=4
    ctx_mma_kernel<<<g2, 256, G2_SMEM>>>(lengths, ctx);
}